// round 16
// baseline (speedup 1.0000x reference)
#include <cuda_runtime.h>
#include <cuda_fp16.h>
#include <cstdint>

#define N_NODES 100000
#define N_EDGES 1600000
#define HID 64
#define NG 512
#define NCLS 10
#define NCODE 1024          // 64 shapes x 16 colors
#define SCAN_BS 512
#define SCAN_NB ((N_NODES + SCAN_BS - 1) / SCAN_BS)   // 196
#define IDMASK 0xFFFFFu     // low 20 bits: node id; high bits: code

#define NB_COUNT (N_EDGES / 256)                 // 6250
#define NB_CODE  ((N_NODES + 255) / 256)         // 391
#define NB_PREP  ((NCODE * 8 + 2 * 4096) / 256)  // 64

// ---------------- device scratch (no allocations allowed) -------------------
// NOTE: g_cnt and g_pool rely on zero-at-load + self-restoring kernels
// (k_scan1 zeroes g_cnt after reading; k_final zeroes g_pool after reading).
__device__ __half g_h1[N_NODES * HID];
__device__ __half g_agg[N_NODES * HID];
__device__ __half g_wT[4 * 4096];   // wT[m][n*64+k] = w[k][n], fp16 (m=2,3 used)
__device__ __align__(16) __half g_y[NCODE * HID];    // 128 KB: code -> h0@w1l (fp16)
__device__ float  g_z2[NCODE * HID];                 // 256 KB: code -> h0@w1r + b1
__device__ int   g_code[N_NODES];
__device__ int   g_cnt[N_NODES];
__device__ int   g_rowptr[N_NODES + 1];
__device__ int   g_cursor[N_NODES];
__device__ int   g_eord[N_EDGES];   // packed: src | (code<<20)
__device__ int   g_part[SCAN_NB];
__device__ float g_pool[NG * HID];

// ---------------------------------------------------------------------------
// Mega-merged prologue: [0,NB_COUNT) in-degree histogram;
// [NB_COUNT, +NB_CODE) node codes; rest: code tables + weight transpose.
__global__ void k_pre(const int* __restrict__ x,
                      const int* __restrict__ ei,
                      const float* __restrict__ semb,
                      const float* __restrict__ cemb,
                      const float* __restrict__ w1l,
                      const float* __restrict__ w1r,
                      const float* __restrict__ b1,
                      const float* __restrict__ w2l,
                      const float* __restrict__ w2r) {
    int b = blockIdx.x;
    int tid = threadIdx.x;
    if (b < NB_COUNT) {
        int e = b * 256 + tid;
        atomicAdd(&g_cnt[ei[N_EDGES + e]], 1);
    } else if (b < NB_COUNT + NB_CODE) {
        int i = (b - NB_COUNT) * 256 + tid;
        if (i < N_NODES) g_code[i] = x[i * 2] * 16 + x[i * 2 + 1];
    } else {
        int id = (b - NB_COUNT - NB_CODE) * 256 + tid;
        if (id < NCODE * 8) {
            int code = id >> 3, jg = id & 7;
            int s = code >> 4, c = code & 15;
            float oy[8], oz[8];
            #pragma unroll
            for (int j = 0; j < 8; j++) { oy[j] = 0.f; oz[j] = 0.f; }
            for (int k = 0; k < 32; k++) {
                float a = semb[s * 32 + k];
                #pragma unroll
                for (int j = 0; j < 8; j++) {
                    oy[j] += a * w1l[k * 64 + jg * 8 + j];
                    oz[j] += a * w1r[k * 64 + jg * 8 + j];
                }
            }
            for (int k = 0; k < 32; k++) {
                float a = cemb[c * 32 + k];
                #pragma unroll
                for (int j = 0; j < 8; j++) {
                    oy[j] += a * w1l[(32 + k) * 64 + jg * 8 + j];
                    oz[j] += a * w1r[(32 + k) * 64 + jg * 8 + j];
                }
            }
            __half2 yh[4];
            #pragma unroll
            for (int q = 0; q < 4; q++)
                yh[q] = __floats2half2_rn(oy[q * 2], oy[q * 2 + 1]);
            *(uint4*)&g_y[code * 64 + jg * 8] = *(uint4*)yh;
            #pragma unroll
            for (int j = 0; j < 8; j++)
                g_z2[code * 64 + jg * 8 + j] = oz[j] + b1[jg * 8 + j];
        } else {
            int t = id - NCODE * 8;
            if (t < 2 * 4096) {
                int m = t >> 12, r = t & 4095;   // m: 0->w2l, 1->w2r
                int k = r >> 6, n = r & 63;
                const float* w = m ? w2r : w2l;
                g_wT[(2 + m) * 4096 + n * 64 + k] = __float2half_rn(w[r]);
            }
        }
    }
}

// Block-local exclusive scan (warp-shuffle), zeroes g_cnt after reading.
__global__ void k_scan1() {
    __shared__ int wsum[16];
    int tid = threadIdx.x, lane = tid & 31, wd = tid >> 5;
    int i = blockIdx.x * SCAN_BS + tid;
    int v = (i < N_NODES) ? g_cnt[i] : 0;
    int inc = v;
    #pragma unroll
    for (int off = 1; off < 32; off <<= 1) {
        int t = __shfl_up_sync(0xffffffffu, inc, off);
        if (lane >= off) inc += t;
    }
    if (lane == 31) wsum[wd] = inc;
    __syncthreads();
    if (wd == 0) {
        int ws = (lane < 16) ? wsum[lane] : 0;
        #pragma unroll
        for (int off = 1; off < 16; off <<= 1) {
            int t = __shfl_up_sync(0xffffffffu, ws, off);
            if (lane >= off) ws += t;
        }
        if (lane < 16) wsum[lane] = ws;   // inclusive warp totals
    }
    __syncthreads();
    int wbase = (wd == 0) ? 0 : wsum[wd - 1];
    if (i < N_NODES) {
        g_rowptr[i] = wbase + inc - v;
        g_cnt[i] = 0;                     // self-restore for next replay
    }
    if (tid == SCAN_BS - 1) g_part[blockIdx.x] = wbase + inc;
}

// Merged scan2+scan3: each block redundantly scans the 196 partials in smem,
// then applies its nodes' block offsets and inits cursors.
__global__ void k_scan23() {
    __shared__ int sp[256];
    __shared__ int sx[256];
    int tid = threadIdx.x;
    int orig = (tid < SCAN_NB) ? g_part[tid] : 0;
    sp[tid] = orig;
    __syncthreads();
    for (int off = 1; off < 256; off <<= 1) {
        int t = (tid >= off) ? sp[tid - off] : 0;
        __syncthreads();
        sp[tid] += t;
        __syncthreads();
    }
    sx[tid] = sp[tid] - orig;   // exclusive prefix of partials
    __syncthreads();
    int i = blockIdx.x * blockDim.x + tid;
    if (i < N_NODES) {
        int r = g_rowptr[i] + sx[i / SCAN_BS];
        g_rowptr[i] = r;
        g_cursor[i] = r;
    }
    if (i == 0) g_rowptr[N_NODES] = N_EDGES;
}

// Bucket edges by target, 4 edges/thread via int4 (MLP across atomic chains);
// single packed scattered store per edge (src | code<<20).
__global__ void k_bucket(const int* __restrict__ ei) {
    int e = blockIdx.x * blockDim.x + threadIdx.x;
    if (e >= N_EDGES / 4) return;
    int4 s4 = ((const int4*)ei)[e];
    int4 t4 = ((const int4*)(ei + N_EDGES))[e];
    int c0 = g_code[s4.x];
    int c1 = g_code[s4.y];
    int c2 = g_code[s4.z];
    int c3 = g_code[s4.w];
    int p0 = atomicAdd(&g_cursor[t4.x], 1);
    int p1 = atomicAdd(&g_cursor[t4.y], 1);
    int p2 = atomicAdd(&g_cursor[t4.z], 1);
    int p3 = atomicAdd(&g_cursor[t4.w], 1);
    g_eord[p0] = s4.x | (c0 << 20);
    g_eord[p1] = s4.y | (c1 << 20);
    g_eord[p2] = s4.z | (c2 << 20);
    g_eord[p3] = s4.w | (c3 << 20);
}

// ---------------------------------------------------------------------------
// Layer 1 (fully fused, table-based):
// h1[n] = relu( mean_{src in N(n)} y[code[src]] + z2[code[n]] )
__global__ void __launch_bounds__(256) k_l1(void) {
    int w = (blockIdx.x * blockDim.x + threadIdx.x) >> 5;
    int lane = threadIdx.x & 31;
    if (w >= N_NODES) return;
    int start = g_rowptr[w], end = g_rowptr[w + 1];
    int deg = end - start;
    int eg = lane >> 3;        // edge subgroup 0..3
    int dg = lane & 7;         // dim group: halves [dg*8, dg*8+8)

    float acc[8];
    #pragma unroll
    for (int i = 0; i < 8; i++) acc[i] = 0.f;

    for (int base = start; base < end; base += 32) {
        int p = base + lane;
        int ev = (p < end) ? g_eord[p] : 0;
        int m = min(32, end - base);
        int fullc = m >> 2;
        int c = 0;
        #pragma unroll 4
        for (; c < fullc; c++) {
            int code = ((unsigned)__shfl_sync(0xffffffffu, ev, c * 4 + eg)) >> 20;
            uint4 v = *(const uint4*)&g_y[code * 64 + dg * 8];
            __half2* hv = (__half2*)&v;
            #pragma unroll
            for (int q = 0; q < 4; q++) {
                float2 f = __half22float2(hv[q]);
                acc[q * 2]     += f.x;
                acc[q * 2 + 1] += f.y;
            }
        }
        if (c * 4 < m) {
            int j = c * 4 + eg;
            int code = ((unsigned)__shfl_sync(0xffffffffu, ev, j)) >> 20;
            uint4 v = *(const uint4*)&g_y[code * 64 + dg * 8];
            if (j < m) {
                __half2* hv = (__half2*)&v;
                #pragma unroll
                for (int q = 0; q < 4; q++) {
                    float2 f = __half22float2(hv[q]);
                    acc[q * 2]     += f.x;
                    acc[q * 2 + 1] += f.y;
                }
            }
        }
    }

    #pragma unroll
    for (int i = 0; i < 8; i++) {
        acc[i] += __shfl_xor_sync(0xffffffffu, acc[i], 8);
        acc[i] += __shfl_xor_sync(0xffffffffu, acc[i], 16);
    }
    if (lane < 8) {
        float inv = 1.f / (float)max(deg, 1);
        int cn = g_code[w];
        float4 z0 = *(const float4*)&g_z2[cn * 64 + dg * 8];
        float4 z1 = *(const float4*)&g_z2[cn * 64 + dg * 8 + 4];
        float o[8];
        o[0] = fmaxf(acc[0] * inv + z0.x, 0.f);
        o[1] = fmaxf(acc[1] * inv + z0.y, 0.f);
        o[2] = fmaxf(acc[2] * inv + z0.z, 0.f);
        o[3] = fmaxf(acc[3] * inv + z0.w, 0.f);
        o[4] = fmaxf(acc[4] * inv + z1.x, 0.f);
        o[5] = fmaxf(acc[5] * inv + z1.y, 0.f);
        o[6] = fmaxf(acc[6] * inv + z1.z, 0.f);
        o[7] = fmaxf(acc[7] * inv + z1.w, 0.f);
        __half2 oh[4];
        #pragma unroll
        for (int q = 0; q < 4; q++)
            oh[q] = __floats2half2_rn(o[q * 2], o[q * 2 + 1]);
        *(uint4*)&g_h1[(size_t)w * 64 + dg * 8] = *(uint4*)oh;
    }
}

// ---------------------------------------------------------------------------
// Layer-2 CSR gather (fp16): agg[n] = mean_{s in N(n)} h1[s].
__global__ void __launch_bounds__(256) k_gather(void) {
    int w = (blockIdx.x * blockDim.x + threadIdx.x) >> 5;
    int lane = threadIdx.x & 31;
    if (w >= N_NODES) return;
    int start = g_rowptr[w], end = g_rowptr[w + 1];
    int deg = end - start;
    const __half* __restrict__ h = g_h1;
    int eg = lane >> 3;
    int dg = lane & 7;

    float acc[8];
    #pragma unroll
    for (int i = 0; i < 8; i++) acc[i] = 0.f;

    for (int base = start; base < end; base += 32) {
        int p = base + lane;
        int ev = (p < end) ? g_eord[p] : 0;
        int m = min(32, end - base);
        int fullc = m >> 2;
        int c = 0;
        #pragma unroll 4
        for (; c < fullc; c++) {
            int s = __shfl_sync(0xffffffffu, ev, c * 4 + eg) & IDMASK;
            uint4 v = *(const uint4*)&h[(size_t)s * 64 + dg * 8];
            __half2* hv = (__half2*)&v;
            #pragma unroll
            for (int q = 0; q < 4; q++) {
                float2 f = __half22float2(hv[q]);
                acc[q * 2]     += f.x;
                acc[q * 2 + 1] += f.y;
            }
        }
        if (c * 4 < m) {
            int j = c * 4 + eg;
            int s = __shfl_sync(0xffffffffu, ev, j) & IDMASK;
            uint4 v = *(const uint4*)&h[(size_t)s * 64 + dg * 8];
            if (j < m) {
                __half2* hv = (__half2*)&v;
                #pragma unroll
                for (int q = 0; q < 4; q++) {
                    float2 f = __half22float2(hv[q]);
                    acc[q * 2]     += f.x;
                    acc[q * 2 + 1] += f.y;
                }
            }
        }
    }

    #pragma unroll
    for (int i = 0; i < 8; i++) {
        acc[i] += __shfl_xor_sync(0xffffffffu, acc[i], 8);
        acc[i] += __shfl_xor_sync(0xffffffffu, acc[i], 16);
    }
    if (lane < 8) {
        float inv = 1.f / (float)max(deg, 1);
        __half2 o[4];
        #pragma unroll
        for (int q = 0; q < 4; q++)
            o[q] = __floats2half2_rn(acc[q * 2] * inv, acc[q * 2 + 1] * inv);
        *(uint4*)&g_agg[(size_t)w * 64 + dg * 8] = *(uint4*)o;
    }
}

// ---------------------------------------------------------------------------
// Layer-2 HMMA update + pool. Warp-uniform pooling fast path.
__global__ void __launch_bounds__(256) k_upd(const float* __restrict__ bias,
                                             const int* __restrict__ batch) {
    __shared__ float sbias[64];
    int tid = threadIdx.x;
    int wid = tid >> 5, lane = tid & 31;
    if (tid < 64) sbias[tid] = bias[tid];
    __syncthreads();

    int m0 = blockIdx.x * 128 + wid * 16;
    int qp = (lane & 3) * 2;
    int gi = lane >> 2;
    int r0 = m0 + gi;
    int r1 = r0 + 8;
    bool v0 = r0 < N_NODES, v1 = r1 < N_NODES;

    float acc[8][4];
    #pragma unroll
    for (int t = 0; t < 8; t++)
        #pragma unroll
        for (int i = 0; i < 4; i++) acc[t][i] = 0.f;

    #pragma unroll
    for (int kc = 0; kc < 2; kc++) {
        const __half* __restrict__ X = kc ? g_h1 : g_agg;
        const __half* __restrict__ W = &g_wT[(2 + kc) * 4096];
        #pragma unroll
        for (int ks = 0; ks < 4; ks++) {
            int kb = ks * 16;
            uint32_t a0 = 0, a1 = 0, a2 = 0, a3 = 0;
            if (v0) {
                a0 = *(const uint32_t*)&X[(size_t)r0 * 64 + kb + qp];
                a2 = *(const uint32_t*)&X[(size_t)r0 * 64 + kb + qp + 8];
            }
            if (v1) {
                a1 = *(const uint32_t*)&X[(size_t)r1 * 64 + kb + qp];
                a3 = *(const uint32_t*)&X[(size_t)r1 * 64 + kb + qp + 8];
            }
            #pragma unroll
            for (int t = 0; t < 8; t++) {
                int n = t * 8 + gi;
                uint32_t b0 = *(const uint32_t*)&W[n * 64 + kb + qp];
                uint32_t b1 = *(const uint32_t*)&W[n * 64 + kb + qp + 8];
                asm volatile(
                    "mma.sync.aligned.m16n8k16.row.col.f32.f16.f16.f32 "
                    "{%0,%1,%2,%3}, {%4,%5,%6,%7}, {%8,%9}, {%0,%1,%2,%3};"
                    : "+f"(acc[t][0]), "+f"(acc[t][1]),
                      "+f"(acc[t][2]), "+f"(acc[t][3])
                    : "r"(a0), "r"(a1), "r"(a2), "r"(a3), "r"(b0), "r"(b1));
            }
        }
    }

    // bias + relu
    #pragma unroll
    for (int t = 0; t < 8; t++) {
        int ct = t * 8 + qp;
        float bx = sbias[ct], by = sbias[ct + 1];
        acc[t][0] = fmaxf(acc[t][0] + bx, 0.f);
        acc[t][1] = fmaxf(acc[t][1] + by, 0.f);
        acc[t][2] = fmaxf(acc[t][2] + bx, 0.f);
        acc[t][3] = fmaxf(acc[t][3] + by, 0.f);
    }

    bool uni = (m0 + 15 < N_NODES) && (batch[m0] == batch[m0 + 15]);
    if (uni) {
        int bg = batch[m0];
        #pragma unroll
        for (int t = 0; t < 8; t++) {
            float s0 = acc[t][0] + acc[t][2];
            float s1 = acc[t][1] + acc[t][3];
            s0 += __shfl_xor_sync(0xffffffffu, s0, 4);
            s1 += __shfl_xor_sync(0xffffffffu, s1, 4);
            s0 += __shfl_xor_sync(0xffffffffu, s0, 8);
            s1 += __shfl_xor_sync(0xffffffffu, s1, 8);
            s0 += __shfl_xor_sync(0xffffffffu, s0, 16);
            s1 += __shfl_xor_sync(0xffffffffu, s1, 16);
            if (lane < 4)
                atomicAdd((float2*)&g_pool[bg * 64 + t * 8 + qp],
                          make_float2(s0, s1));
        }
    } else {
        int b0g = v0 ? batch[r0] : 0;
        int b1g = v1 ? batch[r1] : 0;
        #pragma unroll
        for (int t = 0; t < 8; t++) {
            int ct = t * 8 + qp;
            if (v0) atomicAdd((float2*)&g_pool[b0g * 64 + ct],
                              make_float2(acc[t][0], acc[t][1]));
            if (v1) atomicAdd((float2*)&g_pool[b1g * 64 + ct],
                              make_float2(acc[t][2], acc[t][3]));
        }
    }
}

// ---------------------------------------------------------------------------
// Classifier; per-graph counts via binary search (batch sorted).
// Zeroes g_pool after reading (self-restore for next replay).
__global__ void k_final(const int* __restrict__ batch,
                        const float* __restrict__ wc,
                        const float* __restrict__ bc,
                        float* __restrict__ out) {
    int g = blockIdx.x * blockDim.x + threadIdx.x;
    if (g >= NG) return;
    int lo = 0, hi = N_NODES;
    while (lo < hi) { int mid = (lo + hi) >> 1; if (batch[mid] < g) lo = mid + 1; else hi = mid; }
    int lb = lo;
    hi = N_NODES;
    while (lo < hi) { int mid = (lo + hi) >> 1; if (batch[mid] < g + 1) lo = mid + 1; else hi = mid; }
    int cnt = lo - lb;
    float inv = 1.f / fmaxf((float)cnt, 1.f);
    float acc[NCLS];
    #pragma unroll
    for (int c = 0; c < NCLS; c++) acc[c] = bc[c];
    for (int k = 0; k < 64; k++) {
        float p = g_pool[g * 64 + k] * inv;
        g_pool[g * 64 + k] = 0.f;          // self-restore
        #pragma unroll
        for (int c = 0; c < NCLS; c++)
            acc[c] += p * wc[k * NCLS + c];
    }
    #pragma unroll
    for (int c = 0; c < NCLS; c++) out[g * NCLS + c] = acc[c];
}

// ---------------------------------------------------------------------------
extern "C" void kernel_launch(void* const* d_in, const int* in_sizes, int n_in,
                              void* d_out, int out_size) {
    int o = (n_in >= 14) ? 1 : 0;
    const int*   x     = (const int*)d_in[0];
    const int*   ei    = (const int*)d_in[1];
    const int*   batch = (const int*)d_in[2];
    const float* semb  = (const float*)d_in[3 + o];
    const float* cemb  = (const float*)d_in[4 + o];
    const float* w1l   = (const float*)d_in[5 + o];
    const float* w1r   = (const float*)d_in[6 + o];
    const float* b1    = (const float*)d_in[7 + o];
    const float* w2l   = (const float*)d_in[8 + o];
    const float* w2r   = (const float*)d_in[9 + o];
    const float* b2    = (const float*)d_in[10 + o];
    const float* wc    = (const float*)d_in[11 + o];
    const float* bc    = (const float*)d_in[12 + o];
    float* out = (float*)d_out;

    k_pre<<<NB_COUNT + NB_CODE + NB_PREP, 256>>>(x, ei, semb, cemb,
                                                 w1l, w1r, b1, w2l, w2r);
    k_scan1<<<SCAN_NB, SCAN_BS>>>();
    k_scan23<<<(N_NODES + 255) / 256, 256>>>();
    k_bucket<<<(N_EDGES / 4 + 255) / 256, 256>>>(ei);
    // layer 1: fully fused via code tables
    k_l1<<<(N_NODES * 32 + 255) / 256, 256>>>();
    // layer 2
    k_gather<<<(N_NODES * 32 + 255) / 256, 256>>>();
    k_upd<<<(N_NODES + 127) / 128, 256>>>(b2, batch);
    // pool -> classifier
    k_final<<<(NG + 255) / 256, 256>>>(batch, wc, bc, out);
}